// round 2
// baseline (speedup 1.0000x reference)
#include <cuda_runtime.h>
#include <math.h>

// ---------------------------------------------------------------------------
// Problem constants
// ---------------------------------------------------------------------------
#define kD   256
#define kB   4
#define kS   8192
#define kNE  2048
#define kNC  512
#define kWIN 4
#define kM   (kB * kS)            // 32768 total s rows

#define S_SC       0.25f
#define SC_B       0.2f           // ALPHA * B_SC
#define SC_X       0.075f         // ALPHA * BB2S * X_SC == ALPHA * BS2B * X_SC
#define EPSL       1e-5f
#define INV_SQRT_D 0.0625f
#define CAP        2048           // bucket capacity per (b, target)

// output layout offsets (floats)
#define OFF_SSTATE ((size_t)0)
#define OFF_SVAL   ((size_t)kB * kS * kD)                  //  8388608
#define OFF_NCS    ((size_t)2 * kB * kS * kD)              // 16777216
#define OFF_NCV    (OFF_NCS + (size_t)kB * kNC * kD)       // 17301504

// ---------------------------------------------------------------------------
// Device scratch (static allocation only — no cudaMalloc allowed)
// ---------------------------------------------------------------------------
__device__ float g_logits[(size_t)kM * kNC];           // 64 MB
__device__ float g_scmat[(size_t)kB * kNC * kNC];      //  4 MB
__device__ int   g_entR[(size_t)kB * kNC * CAP];       // 16 MB
__device__ float g_entW[(size_t)kB * kNC * CAP];       // 16 MB
__device__ int   g_cnt[kB * kNC];
__device__ float g_esum[kD];
__device__ int   g_is[4]; __device__ float g_ws[4];    // top4(b_b2s)
__device__ int   g_ic[4]; __device__ float g_wc[4];    // top4(b_comp)
__device__ float g_ncs[(size_t)kB * kNC * kD];         // nc_state pre (scatter result)
__device__ float g_ncv[(size_t)kB * kNC * kD];         // nc_val pre

__device__ __forceinline__ bool bet(float v, int i, float bv, int bi) {
    // jax.lax.top_k tie-break: larger value wins; on tie, lower index wins
    return (v > bv) || (v == bv && i < bi);
}

// ---------------------------------------------------------------------------
// K0: tiny prep kernel (1 block, 256 threads).
// Computes top4 of the three bias vectors, the collapsed e_val row-sum
// (g_esum), and zeroes the scatter counters.
// ---------------------------------------------------------------------------
__global__ __launch_bounds__(256) void k0_prep(
    const float* __restrict__ b_expand, const float* __restrict__ b_b2s,
    const float* __restrict__ b_comp,   const float* __restrict__ ln_b_c,
    const float* __restrict__ ln_g_e,   const float* __restrict__ ln_b_e)
{
    __shared__ float sv[256];  __shared__ int si[256];
    __shared__ float red[256];
    __shared__ float tv[4];    __shared__ int ti[4];
    __shared__ float we[4];    __shared__ int ie[4];
    int tid = threadIdx.x;

    for (int j = tid; j < kB * kNC; j += 256) g_cnt[j] = 0;

    auto top4 = [&](const float* x, int n) {
        for (int r = 0; r < 4; r++) {
            float bv = -INFINITY; int bi = 0x7fffffff;
            for (int j = tid; j < n; j += 256) {
                bool skip = false;
                for (int q = 0; q < r; q++) if (ti[q] == j) skip = true;
                float v = x[j];
                if (!skip && bet(v, j, bv, bi)) { bv = v; bi = j; }
            }
            sv[tid] = bv; si[tid] = bi; __syncthreads();
            for (int s = 128; s > 0; s >>= 1) {
                if (tid < s && bet(sv[tid + s], si[tid + s], sv[tid], si[tid])) {
                    sv[tid] = sv[tid + s]; si[tid] = si[tid + s];
                }
                __syncthreads();
            }
            if (tid == 0) { tv[r] = sv[0]; ti[r] = si[0]; }
            __syncthreads();
        }
    };
    auto softmax4 = [&](float* wout) {
        if (tid == 0) {
            float m = tv[0];  // descending order -> max first
            float e0 = expf(tv[0] - m), e1 = expf(tv[1] - m);
            float e2 = expf(tv[2] - m), e3 = expf(tv[3] - m);
            float inv = 1.0f / (e0 + e1 + e2 + e3);
            wout[0] = e0 * inv; wout[1] = e1 * inv;
            wout[2] = e2 * inv; wout[3] = e3 * inv;
        }
        __syncthreads();
    };

    top4(b_expand, kNE);
    softmax4(we);
    if (tid < 4) ie[tid] = ti[tid];
    __syncthreads();

    top4(b_b2s, kS);
    softmax4(g_ws);
    if (tid < 4) g_is[tid] = ti[tid];
    __syncthreads();

    top4(b_comp, kNC);
    softmax4(g_wc);
    if (tid < 4) g_ic[tid] = ti[tid];
    __syncthreads();

    // ---- collapsed e_val algebra (e_state == 0 throughout) ----
    int d = tid;
    float cval = ln_b_c[d];                       // c_val row = LN(zeros) = ln_b_c
    float rowval[4];
    float dvE = 0.0f;
    #pragma unroll
    for (int j = 0; j < 4; j++) {
        rowval[j] = SC_B * (float)kNC * we[j] * cval;   // e_val row at index ie[j]
        if (ie[j] < 4) dvE += rowval[j];                // topk_prop on zeros picks rows 0..3
    }
    dvE *= 0.25f;
    float base = SC_B * dvE;

    auto bsum = [&](float x) -> float {
        red[tid] = x; __syncthreads();
        for (int s = 128; s > 0; s >>= 1) {
            if (tid < s) red[tid] += red[tid + s];
            __syncthreads();
        }
        float r = red[0]; __syncthreads(); return r;
    };
    float ge = ln_g_e[d], be = ln_b_e[d];
    auto LN_e = [&](float x) -> float {
        float m  = bsum(x) * (1.0f / kD);
        float dv = x - m;
        float var = bsum(dv * dv) * (1.0f / kD);
        return dv * rsqrtf(var + EPSL) * ge + be;
    };

    float other = LN_e(base);
    float esum = (float)(kNE - 4) * other;
    #pragma unroll
    for (int j = 0; j < 4; j++) esum += LN_e(rowval[j] + base);
    g_esum[d] = esum;
}

// ---------------------------------------------------------------------------
// K2: window prop over s, then fused step-5 finalize:
//   s_state_out = tanh(tanh(s + 0.25*ds))
//   s_val_out   = LN( LN(s_val + 0.25*dv) + [n in top4(b_b2s)] 0.075*w*esum )
// one block per (b, n), tid == d
// ---------------------------------------------------------------------------
__global__ __launch_bounds__(256) void k2_window(
    const float* __restrict__ s_state, const float* __restrict__ s_val,
    const float* __restrict__ w_pair_s,
    const float* __restrict__ ln_g_s, const float* __restrict__ ln_b_s,
    float* __restrict__ out)
{
    int row = blockIdx.x;
    int b = row / kS, n = row % kS;
    int d = threadIdx.x;
    const float* st = s_state + (size_t)b * kS * kD;
    const float* vl = s_val   + (size_t)b * kS * kD;

    __shared__ float sred[9 * 8];
    __shared__ float ssc[9];
    __shared__ float red[256];

    float s0 = st[(size_t)n * kD + d];
    float q = s0 * w_pair_s[d];
    float nb[9];
    float part[9];
    #pragma unroll
    for (int k = 0; k < 9; k++) {
        int j = n + k - kWIN;
        int jc = min(max(j, 0), kS - 1);
        nb[k] = st[(size_t)jc * kD + d];
        part[k] = q * nb[k];
    }
    int lane = d & 31, w = d >> 5;
    #pragma unroll
    for (int k = 0; k < 9; k++) {
        float v = part[k];
        #pragma unroll
        for (int off = 16; off > 0; off >>= 1) v += __shfl_down_sync(0xffffffffu, v, off);
        if (lane == 0) sred[k * 8 + w] = v;
    }
    __syncthreads();
    if (d < 9) {
        float v = 0.0f;
        #pragma unroll
        for (int i = 0; i < 8; i++) v += sred[d * 8 + i];
        int j = n + d - kWIN;
        ssc[d] = (j >= 0 && j < kS) ? v * INV_SQRT_D : -INFINITY;
    }
    __syncthreads();

    float mx = -INFINITY;
    #pragma unroll
    for (int k = 0; k < 9; k++) mx = fmaxf(mx, ssc[k]);
    float a[9]; float asum = 0.0f;
    #pragma unroll
    for (int k = 0; k < 9; k++) { a[k] = expf(ssc[k] - mx); asum += a[k]; }
    float ainv = 1.0f / asum;

    float ds = 0.0f, dvv = 0.0f;
    #pragma unroll
    for (int k = 0; k < 9; k++) {
        float ak = a[k] * ainv;
        ds += ak * nb[k];
        int j = n + k - kWIN;
        int jc = min(max(j, 0), kS - 1);
        dvv += ak * vl[(size_t)jc * kD + d];
    }

    float st1 = tanhf(s0 + S_SC * ds);
    out[OFF_SSTATE + (size_t)row * kD + d] = tanhf(st1);   // step-5 ds == 0

    auto bsum = [&](float x) -> float {
        red[d] = x; __syncthreads();
        for (int s = 128; s > 0; s >>= 1) {
            if (d < s) red[d] += red[d + s];
            __syncthreads();
        }
        float r = red[0]; __syncthreads(); return r;
    };
    float gs = ln_g_s[d], bs = ln_b_s[d];

    float v1 = vl[(size_t)n * kD + d] + S_SC * dvv;
    float m1 = bsum(v1) * (1.0f / kD);
    float x1 = v1 - m1;
    float var1 = bsum(x1 * x1) * (1.0f / kD);
    float sv1 = x1 * rsqrtf(var1 + EPSL) * gs + bs;

    #pragma unroll
    for (int j = 0; j < 4; j++)
        if (g_is[j] == n) sv1 += SC_X * g_ws[j] * g_esum[d];

    float m2 = bsum(sv1) * (1.0f / kD);
    float x2 = sv1 - m2;
    float var2 = bsum(x2 * x2) * (1.0f / kD);
    out[OFF_SVAL + (size_t)row * kD + d] = x2 * rsqrtf(var2 + EPSL) * gs + bs;
}

// ---------------------------------------------------------------------------
// K3a: logits GEMM  C[32768,512] = s_state_final @ W_s2b + b_s2b  (fp32 SIMT)
// 128x128x8 tile, 256 threads, 8x8 per thread
// ---------------------------------------------------------------------------
#define GBM 128
#define GBN 128
#define GBK 8
__global__ __launch_bounds__(256) void k3a_gemm(
    const float* __restrict__ A,     // [kM, 256] (s_state_final in d_out)
    const float* __restrict__ W,     // [256, 512]
    const float* __restrict__ bias)  // [512]
{
    __shared__ float As[GBK][GBM + 4];
    __shared__ float Bs[GBK][GBN + 4];
    int tid = threadIdx.x;
    int m0 = blockIdx.y * GBM;
    int n0 = blockIdx.x * GBN;
    int ty = tid / 16, tx = tid % 16;
    float acc[8][8] = {};

    int arow = tid >> 1;
    int acol = (tid & 1) * 4;
    int brow = tid >> 5;
    int bcol = (tid & 31) * 4;

    for (int k0 = 0; k0 < kD; k0 += GBK) {
        float4 av = *(const float4*)&A[(size_t)(m0 + arow) * kD + k0 + acol];
        float4 bv = *(const float4*)&W[(size_t)(k0 + brow) * kNC + n0 + bcol];
        As[acol + 0][arow] = av.x; As[acol + 1][arow] = av.y;
        As[acol + 2][arow] = av.z; As[acol + 3][arow] = av.w;
        *(float4*)&Bs[brow][bcol] = bv;
        __syncthreads();
        #pragma unroll
        for (int kk = 0; kk < GBK; kk++) {
            float ar[8], br[8];
            #pragma unroll
            for (int i = 0; i < 8; i++) ar[i] = As[kk][ty * 8 + i];
            #pragma unroll
            for (int j = 0; j < 8; j++) br[j] = Bs[kk][tx * 8 + j];
            #pragma unroll
            for (int i = 0; i < 8; i++)
                #pragma unroll
                for (int j = 0; j < 8; j++)
                    acc[i][j] += ar[i] * br[j];
        }
        __syncthreads();
    }
    #pragma unroll
    for (int i = 0; i < 8; i++) {
        int m = m0 + ty * 8 + i;
        #pragma unroll
        for (int j = 0; j < 8; j++) {
            int c = n0 + tx * 8 + j;
            g_logits[(size_t)m * kNC + c] = acc[i][j] + bias[c];
        }
    }
}

// ---------------------------------------------------------------------------
// K3b: per-row top-4 over 512 logits (warp per row) + bucket entries
// ---------------------------------------------------------------------------
__global__ __launch_bounds__(256) void k3b_top4()
{
    int warp = threadIdx.x >> 5, lane = threadIdx.x & 31;
    int row = blockIdx.x * 8 + warp;
    int b = row / kS;
    const float* lg = g_logits + (size_t)row * kNC;

    float tv[4] = {-INFINITY, -INFINITY, -INFINITY, -INFINITY};
    int   ti[4] = {0x7fffffff, 0x7fffffff, 0x7fffffff, 0x7fffffff};
    #pragma unroll
    for (int t = 0; t < 16; t++) {
        int c = lane + t * 32;
        float v = lg[c];
        if (bet(v, c, tv[3], ti[3])) {
            tv[3] = v; ti[3] = c;
            for (int q = 3; q > 0; q--) {
                if (bet(tv[q], ti[q], tv[q - 1], ti[q - 1])) {
                    float fv = tv[q]; tv[q] = tv[q - 1]; tv[q - 1] = fv;
                    int   fi = ti[q]; ti[q] = ti[q - 1]; ti[q - 1] = fi;
                } else break;
            }
        }
    }
    float topv[4]; int topi[4];
    #pragma unroll
    for (int r = 0; r < 4; r++) {
        float v = tv[0]; int i = ti[0];
        #pragma unroll
        for (int off = 16; off > 0; off >>= 1) {
            float ov = __shfl_down_sync(0xffffffffu, v, off);
            int   oi = __shfl_down_sync(0xffffffffu, i, off);
            if (bet(ov, oi, v, i)) { v = ov; i = oi; }
        }
        v = __shfl_sync(0xffffffffu, v, 0);
        i = __shfl_sync(0xffffffffu, i, 0);
        topv[r] = v; topi[r] = i;
        if (ti[0] == i) {
            tv[0] = tv[1]; ti[0] = ti[1];
            tv[1] = tv[2]; ti[1] = ti[2];
            tv[2] = tv[3]; ti[2] = ti[3];
            tv[3] = -INFINITY; ti[3] = 0x7fffffff;
        }
    }
    float mx = topv[0];
    float e0 = expf(topv[0] - mx), e1 = expf(topv[1] - mx);
    float e2 = expf(topv[2] - mx), e3 = expf(topv[3] - mx);
    float inv = 1.0f / (e0 + e1 + e2 + e3);
    if (lane < 4) {
        float ej = (lane == 0) ? e0 : (lane == 1) ? e1 : (lane == 2) ? e2 : e3;
        float wgt = SC_X * ej * inv;
        int t = topi[lane];
        int bt = b * kNC + t;
        int pos = atomicAdd(&g_cnt[bt], 1);
        if (pos < CAP) {
            g_entR[(size_t)bt * CAP + pos] = row;
            g_entW[(size_t)bt * CAP + pos] = wgt;
        }
    }
}

// ---------------------------------------------------------------------------
// K3c: per-(b,target) gather-sum -> nc_state_pre / nc_val_pre (no float atomics)
// ---------------------------------------------------------------------------
__global__ __launch_bounds__(256) void k3c_gather(
    const float* __restrict__ out,        // d_out (reads s_state/s_val final)
    const float* __restrict__ ln_b_c)
{
    int bt = blockIdx.x;
    int t = bt % kNC;
    int d = threadIdx.x;
    int n = min(g_cnt[bt], CAP);
    const float* ssf = out + OFF_SSTATE;
    const float* svf = out + OFF_SVAL;
    float accS = 0.0f, accV = 0.0f;
    #pragma unroll 4
    for (int i = 0; i < n; i++) {
        int r   = g_entR[(size_t)bt * CAP + i];
        float w = g_entW[(size_t)bt * CAP + i];
        accS += w * ssf[(size_t)r * kD + d];
        accV += w * svf[(size_t)r * kD + d];
    }
    g_ncs[(size_t)bt * kD + d] = accS;
    float nv0 = ln_b_c[d];
    #pragma unroll
    for (int j = 0; j < 4; j++)
        if (g_ic[j] == t) nv0 += SC_B * g_wc[j] * g_esum[d];
    g_ncv[(size_t)bt * kD + d] = nv0 + accV;
}

// ---------------------------------------------------------------------------
// K4a: per-batch scores  sc = (ncs*w_pair_c) @ ncs^T * INV_SQRT_D  (512x512)
// 64x64x16 tile, 256 threads, 4x4 per thread
// ---------------------------------------------------------------------------
__global__ __launch_bounds__(256) void k4a_scores(const float* __restrict__ wpc)
{
    int bb = blockIdx.z;
    int m0 = blockIdx.y * 64;
    int n0 = blockIdx.x * 64;
    const float* ncs = g_ncs + (size_t)bb * kNC * kD;
    __shared__ float As[16][64 + 4];
    __shared__ float Bs[16][64 + 4];
    int tid = threadIdx.x;
    int ty = tid / 16, tx = tid % 16;
    float acc[4][4] = {};
    int lrow = tid / 4;
    int lk = (tid % 4) * 4;
    for (int k0 = 0; k0 < kD; k0 += 16) {
        float4 av = *(const float4*)&ncs[(size_t)(m0 + lrow) * kD + k0 + lk];
        float4 bv = *(const float4*)&ncs[(size_t)(n0 + lrow) * kD + k0 + lk];
        float4 wv = *(const float4*)&wpc[k0 + lk];
        As[lk + 0][lrow] = av.x * wv.x; As[lk + 1][lrow] = av.y * wv.y;
        As[lk + 2][lrow] = av.z * wv.z; As[lk + 3][lrow] = av.w * wv.w;
        Bs[lk + 0][lrow] = bv.x; Bs[lk + 1][lrow] = bv.y;
        Bs[lk + 2][lrow] = bv.z; Bs[lk + 3][lrow] = bv.w;
        __syncthreads();
        #pragma unroll
        for (int kk = 0; kk < 16; kk++) {
            float ar[4], br[4];
            #pragma unroll
            for (int i = 0; i < 4; i++) ar[i] = As[kk][ty * 4 + i];
            #pragma unroll
            for (int j = 0; j < 4; j++) br[j] = Bs[kk][tx * 4 + j];
            #pragma unroll
            for (int i = 0; i < 4; i++)
                #pragma unroll
                for (int j = 0; j < 4; j++)
                    acc[i][j] += ar[i] * br[j];
        }
        __syncthreads();
    }
    #pragma unroll
    for (int i = 0; i < 4; i++)
        #pragma unroll
        for (int j = 0; j < 4; j++)
            g_scmat[(size_t)bb * kNC * kNC + (size_t)(m0 + ty * 4 + i) * kNC + (n0 + tx * 4 + j)] =
                acc[i][j] * INV_SQRT_D;
}

// ---------------------------------------------------------------------------
// K4b: per-(b,n) top-4 over 512 scores, softmax, gather, tanh/LN finalize
// ---------------------------------------------------------------------------
__global__ __launch_bounds__(256) void k4b_final(
    const float* __restrict__ ln_g_c, const float* __restrict__ ln_b_c,
    float* __restrict__ out)
{
    int bn = blockIdx.x;
    int bb = bn / kNC;
    int d = threadIdx.x;
    const float* sc = g_scmat + (size_t)bn * kNC;
    __shared__ float sv[256]; __shared__ int si[256];
    __shared__ float red[256];
    __shared__ float topw[4]; __shared__ int topidx[4];

    float v0 = sc[d], v1 = sc[d + 256];
    bool t0 = false, t1 = false;
    for (int r = 0; r < 4; r++) {
        float bv = -INFINITY; int bi = 0x7fffffff;
        if (!t0) { bv = v0; bi = d; }
        if (!t1 && bet(v1, d + 256, bv, bi)) { bv = v1; bi = d + 256; }
        sv[d] = bv; si[d] = bi; __syncthreads();
        for (int s = 128; s > 0; s >>= 1) {
            if (d < s && bet(sv[d + s], si[d + s], sv[d], si[d])) {
                sv[d] = sv[d + s]; si[d] = si[d + s];
            }
            __syncthreads();
        }
        if (d == 0) { topw[r] = sv[0]; topidx[r] = si[0]; }
        __syncthreads();
        int widx = topidx[r];
        if (widx == d) t0 = true;
        if (widx == d + 256) t1 = true;
    }

    float mx = topw[0];
    float e[4]; float esum = 0.0f;
    #pragma unroll
    for (int j = 0; j < 4; j++) { e[j] = expf(topw[j] - mx); esum += e[j]; }
    float inv = 1.0f / esum;

    const float* ncsB = g_ncs + (size_t)bb * kNC * kD;
    const float* ncvB = g_ncv + (size_t)bb * kNC * kD;
    float ds = 0.0f, dv = 0.0f;
    #pragma unroll
    for (int j = 0; j < 4; j++) {
        int m = topidx[j];
        float a = e[j] * inv;
        ds += a * ncsB[(size_t)m * kD + d];
        dv += a * ncvB[(size_t)m * kD + d];
    }
    float spre = g_ncs[(size_t)bn * kD + d];
    float vpre = g_ncv[(size_t)bn * kD + d];

    out[OFF_NCS + (size_t)bn * kD + d] = tanhf(spre + SC_B * ds);

    auto bsum = [&](float x) -> float {
        red[d] = x; __syncthreads();
        for (int s = 128; s > 0; s >>= 1) {
            if (d < s) red[d] += red[d + s];
            __syncthreads();
        }
        float r = red[0]; __syncthreads(); return r;
    };
    float x = vpre + SC_B * dv;
    float m = bsum(x) * (1.0f / kD);
    float xd = x - m;
    float var = bsum(xd * xd) * (1.0f / kD);
    out[OFF_NCV + (size_t)bn * kD + d] = xd * rsqrtf(var + EPSL) * ln_g_c[d] + ln_b_c[d];
}

// ---------------------------------------------------------------------------
// kernel_launch
// ---------------------------------------------------------------------------
extern "C" void kernel_launch(void* const* d_in, const int* in_sizes, int n_in,
                              void* d_out, int out_size) {
    const float* s_state  = (const float*)d_in[0];
    const float* s_val    = (const float*)d_in[1];
    const float* w_pair_s = (const float*)d_in[2];
    const float* w_pair_c = (const float*)d_in[4];
    const float* b_expand = (const float*)d_in[6];
    const float* b_b2s    = (const float*)d_in[8];
    const float* b_comp   = (const float*)d_in[10];
    const float* W_s2b    = (const float*)d_in[11];
    const float* b_s2b    = (const float*)d_in[12];
    const float* ln_g_s   = (const float*)d_in[13];
    const float* ln_b_s   = (const float*)d_in[14];
    const float* ln_g_e   = (const float*)d_in[15];
    const float* ln_b_e   = (const float*)d_in[16];
    const float* ln_g_c   = (const float*)d_in[17];
    const float* ln_b_c   = (const float*)d_in[18];
    float* out = (float*)d_out;

    k0_prep<<<1, 256>>>(b_expand, b_b2s, b_comp, ln_b_c, ln_g_e, ln_b_e);
    k2_window<<<kM, 256>>>(s_state, s_val, w_pair_s, ln_g_s, ln_b_s, out);
    dim3 g3a(kNC / GBN, kM / GBM);
    k3a_gemm<<<g3a, 256>>>(out + OFF_SSTATE, W_s2b, b_s2b);
    k3b_top4<<<kM / 8, 256>>>();
    k3c_gather<<<kB * kNC, 256>>>(out, ln_b_c);
    dim3 g4a(kNC / 64, kNC / 64, kB);
    k4a_scores<<<g4a, 256>>>(w_pair_c);
    k4b_final<<<kB * kNC, 256>>>(ln_g_c, ln_b_c, out);
}

// round 3
// speedup vs baseline: 1.6306x; 1.6306x over previous
#include <cuda_runtime.h>
#include <cuda_bf16.h>
#include <math.h>

// ---------------------------------------------------------------------------
#define kD   256
#define kB   4
#define kS   8192
#define kNE  2048
#define kNC  512
#define kWIN 4
#define kM   (kB * kS)

#define S_SC       0.25f
#define SC_B       0.2f
#define SC_X       0.075f
#define EPSL       1e-5f
#define INV_SQRT_D 0.0625f
#define CAP        2048

#define OFF_SSTATE ((size_t)0)
#define OFF_SVAL   ((size_t)kB * kS * kD)
#define OFF_NCS    ((size_t)2 * kB * kS * kD)
#define OFF_NCV    (OFF_NCS + (size_t)kB * kNC * kD)

// ---------------------------------------------------------------------------
__device__ float g_scmat[(size_t)kB * kNC * kNC];
__device__ int   g_entR[(size_t)kB * kNC * CAP];
__device__ float g_entW[(size_t)kB * kNC * CAP];
__device__ int   g_cnt[kB * kNC];
__device__ float g_esum[kD];
__device__ int   g_is[4]; __device__ float g_ws[4];
__device__ int   g_ic[4]; __device__ float g_wc[4];
__device__ float g_ncs[(size_t)kB * kNC * kD];
__device__ float g_ncv[(size_t)kB * kNC * kD];

__device__ __nv_bfloat16 g_shi[(size_t)kM * kD];    // split-bf16 of s_state_final
__device__ __nv_bfloat16 g_slo[(size_t)kM * kD];
__device__ __nv_bfloat16 g_wth[(size_t)kNC * kD];   // W_s2b^T hi  [512][256]
__device__ __nv_bfloat16 g_wtl[(size_t)kNC * kD];   // W_s2b^T lo
__device__ float g_candV[(size_t)kM * 16];          // 4 slabs x 4 candidates
__device__ int   g_candI[(size_t)kM * 16];

__device__ __forceinline__ bool bet(float v, int i, float bv, int bi) {
    return (v > bv) || (v == bv && i < bi);
}

__device__ __forceinline__ float warpsum(float v) {
    #pragma unroll
    for (int off = 16; off > 0; off >>= 1) v += __shfl_xor_sync(0xffffffffu, v, off);
    return v;
}

// sorted-4 insertion (descending by bet)
__device__ __forceinline__ void ins4(float v, int i, float* tv, int* ti) {
    if (bet(v, i, tv[3], ti[3])) {
        tv[3] = v; ti[3] = i;
        #pragma unroll
        for (int q = 3; q > 0; q--) {
            if (bet(tv[q], ti[q], tv[q - 1], ti[q - 1])) {
                float fv = tv[q]; tv[q] = tv[q - 1]; tv[q - 1] = fv;
                int   fi = ti[q]; ti[q] = ti[q - 1]; ti[q - 1] = fi;
            } else break;
        }
    }
}

__device__ __forceinline__ void mma16816(float* c, const unsigned* a, const unsigned* b) {
    asm volatile(
        "mma.sync.aligned.m16n8k16.row.col.f32.bf16.bf16.f32 "
        "{%0,%1,%2,%3}, {%4,%5,%6,%7}, {%8,%9}, {%0,%1,%2,%3};"
        : "+f"(c[0]), "+f"(c[1]), "+f"(c[2]), "+f"(c[3])
        : "r"(a[0]), "r"(a[1]), "r"(a[2]), "r"(a[3]), "r"(b[0]), "r"(b[1]));
}

// ---------------------------------------------------------------------------
// K0: prep (top4 of biases, collapsed e_val algebra, zero counters)
// ---------------------------------------------------------------------------
__global__ __launch_bounds__(256) void k0_prep(
    const float* __restrict__ b_expand, const float* __restrict__ b_b2s,
    const float* __restrict__ b_comp,   const float* __restrict__ ln_b_c,
    const float* __restrict__ ln_g_e,   const float* __restrict__ ln_b_e)
{
    __shared__ float sv[256];  __shared__ int si[256];
    __shared__ float red[256];
    __shared__ float tv[4];    __shared__ int ti[4];
    __shared__ float we[4];    __shared__ int ie[4];
    int tid = threadIdx.x;

    for (int j = tid; j < kB * kNC; j += 256) g_cnt[j] = 0;

    auto top4 = [&](const float* x, int n) {
        for (int r = 0; r < 4; r++) {
            float bv = -INFINITY; int bi = 0x7fffffff;
            for (int j = tid; j < n; j += 256) {
                bool skip = false;
                for (int q = 0; q < r; q++) if (ti[q] == j) skip = true;
                float v = x[j];
                if (!skip && bet(v, j, bv, bi)) { bv = v; bi = j; }
            }
            sv[tid] = bv; si[tid] = bi; __syncthreads();
            for (int s = 128; s > 0; s >>= 1) {
                if (tid < s && bet(sv[tid + s], si[tid + s], sv[tid], si[tid])) {
                    sv[tid] = sv[tid + s]; si[tid] = si[tid + s];
                }
                __syncthreads();
            }
            if (tid == 0) { tv[r] = sv[0]; ti[r] = si[0]; }
            __syncthreads();
        }
    };
    auto softmax4 = [&](float* wout) {
        if (tid == 0) {
            float m = tv[0];
            float e0 = expf(tv[0] - m), e1 = expf(tv[1] - m);
            float e2 = expf(tv[2] - m), e3 = expf(tv[3] - m);
            float inv = 1.0f / (e0 + e1 + e2 + e3);
            wout[0] = e0 * inv; wout[1] = e1 * inv;
            wout[2] = e2 * inv; wout[3] = e3 * inv;
        }
        __syncthreads();
    };

    top4(b_expand, kNE); softmax4(we);
    if (tid < 4) ie[tid] = ti[tid];
    __syncthreads();
    top4(b_b2s, kS); softmax4(g_ws);
    if (tid < 4) g_is[tid] = ti[tid];
    __syncthreads();
    top4(b_comp, kNC); softmax4(g_wc);
    if (tid < 4) g_ic[tid] = ti[tid];
    __syncthreads();

    int d = tid;
    float cval = ln_b_c[d];
    float rowval[4];
    float dvE = 0.0f;
    #pragma unroll
    for (int j = 0; j < 4; j++) {
        rowval[j] = SC_B * (float)kNC * we[j] * cval;
        if (ie[j] < 4) dvE += rowval[j];
    }
    dvE *= 0.25f;
    float base = SC_B * dvE;

    auto bsum = [&](float x) -> float {
        red[tid] = x; __syncthreads();
        for (int s = 128; s > 0; s >>= 1) {
            if (tid < s) red[tid] += red[tid + s];
            __syncthreads();
        }
        float r = red[0]; __syncthreads(); return r;
    };
    float ge = ln_g_e[d], be = ln_b_e[d];
    auto LN_e = [&](float x) -> float {
        float m  = bsum(x) * (1.0f / kD);
        float dv = x - m;
        float var = bsum(dv * dv) * (1.0f / kD);
        return dv * rsqrtf(var + EPSL) * ge + be;
    };

    float other = LN_e(base);
    float esum = (float)(kNE - 4) * other;
    #pragma unroll
    for (int j = 0; j < 4; j++) esum += LN_e(rowval[j] + base);
    g_esum[d] = esum;
}

// ---------------------------------------------------------------------------
// K1: split W_s2b into transposed bf16 hi/lo  [512 n][256 k]
// ---------------------------------------------------------------------------
__global__ void k1_splitW(const float* __restrict__ W)
{
    __shared__ float tile[32][33];
    int n0 = blockIdx.x * 32, k0 = blockIdx.y * 32;
    int tx = threadIdx.x, ty = threadIdx.y;
    tile[ty][tx] = W[(size_t)(k0 + ty) * kNC + n0 + tx];
    __syncthreads();
    float x = tile[tx][ty];                    // W[k0+tx][n0+ty]
    __nv_bfloat16 hi = __float2bfloat16(x);
    float lo = x - __bfloat162float(hi);
    g_wth[(size_t)(n0 + ty) * kD + k0 + tx] = hi;
    g_wtl[(size_t)(n0 + ty) * kD + k0 + tx] = __float2bfloat16(lo);
}

// ---------------------------------------------------------------------------
// K2: warp-per-row window prop + double tanh + double LN; emits bf16 split
// ---------------------------------------------------------------------------
__global__ __launch_bounds__(256) void k2_window(
    const float* __restrict__ s_state, const float* __restrict__ s_val,
    const float* __restrict__ w_pair_s,
    const float* __restrict__ ln_g_s, const float* __restrict__ ln_b_s,
    float* __restrict__ out)
{
    int warp = threadIdx.x >> 5, lane = threadIdx.x & 31;
    int row = blockIdx.x * 8 + warp;
    int b = row >> 13, n = row & (kS - 1);
    const float4* st4 = (const float4*)(s_state + (size_t)b * kS * kD);
    const float4* vl4 = (const float4*)(s_val   + (size_t)b * kS * kD);
    int ci = lane * 2;

    float4 w0 = ((const float4*)w_pair_s)[ci];
    float4 w1 = ((const float4*)w_pair_s)[ci + 1];
    float4 s0a = st4[(size_t)n * 64 + ci];
    float4 s0b = st4[(size_t)n * 64 + ci + 1];
    float4 q0, q1;
    q0.x = s0a.x * w0.x; q0.y = s0a.y * w0.y; q0.z = s0a.z * w0.z; q0.w = s0a.w * w0.w;
    q1.x = s0b.x * w1.x; q1.y = s0b.y * w1.y; q1.z = s0b.z * w1.z; q1.w = s0b.w * w1.w;

    float sc[9];
    #pragma unroll
    for (int k = 0; k < 9; k++) {
        int j = n + k - kWIN;
        bool valid = ((unsigned)j < (unsigned)kS);
        int jc = min(max(j, 0), kS - 1);
        float4 na = st4[(size_t)jc * 64 + ci];
        float4 nb = st4[(size_t)jc * 64 + ci + 1];
        float p = q0.x * na.x + q0.y * na.y + q0.z * na.z + q0.w * na.w
                + q1.x * nb.x + q1.y * nb.y + q1.z * nb.z + q1.w * nb.w;
        p = warpsum(p);
        sc[k] = valid ? p * INV_SQRT_D : -1e30f;
    }
    float mx = sc[0];
    #pragma unroll
    for (int k = 1; k < 9; k++) mx = fmaxf(mx, sc[k]);
    float asum = 0.0f;
    #pragma unroll
    for (int k = 0; k < 9; k++) { sc[k] = expf(sc[k] - mx); asum += sc[k]; }
    float ainv = 1.0f / asum;

    float4 ds0 = {0,0,0,0}, ds1 = {0,0,0,0}, dv0 = {0,0,0,0}, dv1 = {0,0,0,0};
    #pragma unroll
    for (int k = 0; k < 9; k++) {
        int j = n + k - kWIN;
        int jc = min(max(j, 0), kS - 1);
        float a = sc[k] * ainv;
        float4 na = st4[(size_t)jc * 64 + ci];
        float4 nb = st4[(size_t)jc * 64 + ci + 1];
        float4 va = vl4[(size_t)jc * 64 + ci];
        float4 vb = vl4[(size_t)jc * 64 + ci + 1];
        ds0.x += a * na.x; ds0.y += a * na.y; ds0.z += a * na.z; ds0.w += a * na.w;
        ds1.x += a * nb.x; ds1.y += a * nb.y; ds1.z += a * nb.z; ds1.w += a * nb.w;
        dv0.x += a * va.x; dv0.y += a * va.y; dv0.z += a * va.z; dv0.w += a * va.w;
        dv1.x += a * vb.x; dv1.y += a * vb.y; dv1.z += a * vb.z; dv1.w += a * vb.w;
    }

    // s_state: tanh(tanh(s + 0.25 ds))
    float so[8];
    so[0] = tanhf(tanhf(s0a.x + S_SC * ds0.x));
    so[1] = tanhf(tanhf(s0a.y + S_SC * ds0.y));
    so[2] = tanhf(tanhf(s0a.z + S_SC * ds0.z));
    so[3] = tanhf(tanhf(s0a.w + S_SC * ds0.w));
    so[4] = tanhf(tanhf(s0b.x + S_SC * ds1.x));
    so[5] = tanhf(tanhf(s0b.y + S_SC * ds1.y));
    so[6] = tanhf(tanhf(s0b.z + S_SC * ds1.z));
    so[7] = tanhf(tanhf(s0b.w + S_SC * ds1.w));

    float4* outS = (float4*)(out + OFF_SSTATE);
    outS[(size_t)row * 64 + ci]     = make_float4(so[0], so[1], so[2], so[3]);
    outS[(size_t)row * 64 + ci + 1] = make_float4(so[4], so[5], so[6], so[7]);

    // bf16 split write
    uint4 hw, lw;
    unsigned* hwp = (unsigned*)&hw; unsigned* lwp = (unsigned*)&lw;
    #pragma unroll
    for (int i = 0; i < 4; i++) {
        float a = so[2 * i], c = so[2 * i + 1];
        __nv_bfloat16 ha = __float2bfloat16(a), hc = __float2bfloat16(c);
        hwp[i] = ((unsigned)__bfloat16_as_ushort(hc) << 16) | __bfloat16_as_ushort(ha);
        float la = a - __bfloat162float(ha), lc = c - __bfloat162float(hc);
        __nv_bfloat16 bla = __float2bfloat16(la), blc = __float2bfloat16(lc);
        lwp[i] = ((unsigned)__bfloat16_as_ushort(blc) << 16) | __bfloat16_as_ushort(bla);
    }
    *(uint4*)&g_shi[(size_t)row * kD + lane * 8] = hw;
    *(uint4*)&g_slo[(size_t)row * kD + lane * 8] = lw;

    // s_val: LN then sparse add then LN
    float4 va0 = vl4[(size_t)n * 64 + ci];
    float4 va1 = vl4[(size_t)n * 64 + ci + 1];
    float v[8];
    v[0] = va0.x + S_SC * dv0.x; v[1] = va0.y + S_SC * dv0.y;
    v[2] = va0.z + S_SC * dv0.z; v[3] = va0.w + S_SC * dv0.w;
    v[4] = va1.x + S_SC * dv1.x; v[5] = va1.y + S_SC * dv1.y;
    v[6] = va1.z + S_SC * dv1.z; v[7] = va1.w + S_SC * dv1.w;

    float4 g0 = ((const float4*)ln_g_s)[ci], g1 = ((const float4*)ln_g_s)[ci + 1];
    float4 b0v = ((const float4*)ln_b_s)[ci], b1v = ((const float4*)ln_b_s)[ci + 1];
    float gs[8] = {g0.x, g0.y, g0.z, g0.w, g1.x, g1.y, g1.z, g1.w};
    float bs[8] = {b0v.x, b0v.y, b0v.z, b0v.w, b1v.x, b1v.y, b1v.z, b1v.w};

    float s8 = 0.0f;
    #pragma unroll
    for (int i = 0; i < 8; i++) s8 += v[i];
    float mean = warpsum(s8) * (1.0f / kD);
    float vs = 0.0f;
    #pragma unroll
    for (int i = 0; i < 8; i++) { v[i] -= mean; vs += v[i] * v[i]; }
    float rstd = rsqrtf(warpsum(vs) * (1.0f / kD) + EPSL);
    #pragma unroll
    for (int i = 0; i < 8; i++) v[i] = v[i] * rstd * gs[i] + bs[i];

    // sparse add (only rows in top4(b_b2s))
    bool hit = false; float wj = 0.0f;
    #pragma unroll
    for (int j = 0; j < 4; j++)
        if (g_is[j] == n) { hit = true; wj = g_ws[j]; }
    if (hit) {
        float4 e0 = ((const float4*)g_esum)[ci], e1 = ((const float4*)g_esum)[ci + 1];
        float es[8] = {e0.x, e0.y, e0.z, e0.w, e1.x, e1.y, e1.z, e1.w};
        #pragma unroll
        for (int i = 0; i < 8; i++) v[i] += SC_X * wj * es[i];
    }

    s8 = 0.0f;
    #pragma unroll
    for (int i = 0; i < 8; i++) s8 += v[i];
    mean = warpsum(s8) * (1.0f / kD);
    vs = 0.0f;
    #pragma unroll
    for (int i = 0; i < 8; i++) { v[i] -= mean; vs += v[i] * v[i]; }
    rstd = rsqrtf(warpsum(vs) * (1.0f / kD) + EPSL);
    float4* outV = (float4*)(out + OFF_SVAL);
    outV[(size_t)row * 64 + ci] =
        make_float4(v[0] * rstd * gs[0] + bs[0], v[1] * rstd * gs[1] + bs[1],
                    v[2] * rstd * gs[2] + bs[2], v[3] * rstd * gs[3] + bs[3]);
    outV[(size_t)row * 64 + ci + 1] =
        make_float4(v[4] * rstd * gs[4] + bs[4], v[5] * rstd * gs[5] + bs[5],
                    v[6] * rstd * gs[6] + bs[6], v[7] * rstd * gs[7] + bs[7]);
}

// ---------------------------------------------------------------------------
// K3a: split-bf16 tensor-core GEMM (hh+hl+lh) + fused per-slab top4 epilogue
// block tile 128x128, K=256, 8 warps (4 m x 2 n), warp tile 32x64
// ---------------------------------------------------------------------------
__global__ __launch_bounds__(256, 2) void k3a_gemm(const float* __restrict__ bias)
{
    __shared__ __nv_bfloat16 Ah[128][40], Al[128][40], Bh[128][40], Bl[128][40];
    int tid = threadIdx.x;
    int warp = tid >> 5, lane = tid & 31;
    int mw = warp & 3, nw = warp >> 2;
    int g = lane >> 2, t = lane & 3;
    int m0 = blockIdx.y * 128, n0 = blockIdx.x * 128;
    int lr = tid >> 1, seg = tid & 1;

    float acc[2][8][4];
    #pragma unroll
    for (int i = 0; i < 2; i++)
        #pragma unroll
        for (int j = 0; j < 8; j++)
            #pragma unroll
            for (int q = 0; q < 4; q++) acc[i][j][q] = 0.0f;

    for (int k0 = 0; k0 < kD; k0 += 32) {
        {
            const uint4* gAh = (const uint4*)(g_shi + (size_t)(m0 + lr) * kD + k0) + seg * 2;
            const uint4* gAl = (const uint4*)(g_slo + (size_t)(m0 + lr) * kD + k0) + seg * 2;
            const uint4* gBh = (const uint4*)(g_wth + (size_t)(n0 + lr) * kD + k0) + seg * 2;
            const uint4* gBl = (const uint4*)(g_wtl + (size_t)(n0 + lr) * kD + k0) + seg * 2;
            uint4 a0 = gAh[0], a1 = gAh[1];
            uint4 b0 = gAl[0], b1 = gAl[1];
            uint4 c0 = gBh[0], c1 = gBh[1];
            uint4 d0 = gBl[0], d1 = gBl[1];
            *(uint4*)&Ah[lr][seg * 16]     = a0; *(uint4*)&Ah[lr][seg * 16 + 8] = a1;
            *(uint4*)&Al[lr][seg * 16]     = b0; *(uint4*)&Al[lr][seg * 16 + 8] = b1;
            *(uint4*)&Bh[lr][seg * 16]     = c0; *(uint4*)&Bh[lr][seg * 16 + 8] = c1;
            *(uint4*)&Bl[lr][seg * 16]     = d0; *(uint4*)&Bl[lr][seg * 16 + 8] = d1;
        }
        __syncthreads();
        #pragma unroll
        for (int ks = 0; ks < 2; ks++) {
            int kb = ks * 16;
            unsigned ah[2][4], al[2][4];
            #pragma unroll
            for (int mt = 0; mt < 2; mt++) {
                int r = mw * 32 + mt * 16 + g;
                ah[mt][0] = *(const unsigned*)&Ah[r][kb + 2 * t];
                ah[mt][1] = *(const unsigned*)&Ah[r + 8][kb + 2 * t];
                ah[mt][2] = *(const unsigned*)&Ah[r][kb + 2 * t + 8];
                ah[mt][3] = *(const unsigned*)&Ah[r + 8][kb + 2 * t + 8];
                al[mt][0] = *(const unsigned*)&Al[r][kb + 2 * t];
                al[mt][1] = *(const unsigned*)&Al[r + 8][kb + 2 * t];
                al[mt][2] = *(const unsigned*)&Al[r][kb + 2 * t + 8];
                al[mt][3] = *(const unsigned*)&Al[r + 8][kb + 2 * t + 8];
            }
            #pragma unroll
            for (int nt = 0; nt < 8; nt++) {
                int nn = nw * 64 + nt * 8 + g;
                unsigned bh[2], bl[2];
                bh[0] = *(const unsigned*)&Bh[nn][kb + 2 * t];
                bh[1] = *(const unsigned*)&Bh[nn][kb + 2 * t + 8];
                bl[0] = *(const unsigned*)&Bl[nn][kb + 2 * t];
                bl[1] = *(const unsigned*)&Bl[nn][kb + 2 * t + 8];
                #pragma unroll
                for (int mt = 0; mt < 2; mt++) {
                    mma16816(acc[mt][nt], ah[mt], bh);
                    mma16816(acc[mt][nt], ah[mt], bl);
                    mma16816(acc[mt][nt], al[mt], bh);
                }
            }
        }
        __syncthreads();
    }

    // bias per lane-col (16 cols)
    float bcol[16];
    #pragma unroll
    for (int nt = 0; nt < 8; nt++) {
        int c = n0 + nw * 64 + nt * 8 + 2 * t;
        bcol[nt * 2]     = bias[c];
        bcol[nt * 2 + 1] = bias[c + 1];
    }

    // epilogue: per-row top4 within this 128-col slab
    float* svv = (float*)&Ah[0][0];                 // reuse tile smem: 128*2*4 floats
    int*   sii = (int*)(((char*)&Ah[0][0]) + 4096);
    __syncthreads();

    #pragma unroll
    for (int mt = 0; mt < 2; mt++) {
        #pragma unroll
        for (int h = 0; h < 2; h++) {
            float tv[4] = {-INFINITY, -INFINITY, -INFINITY, -INFINITY};
            int   ti[4] = {0x7fffffff, 0x7fffffff, 0x7fffffff, 0x7fffffff};
            #pragma unroll
            for (int nt = 0; nt < 8; nt++) {
                #pragma unroll
                for (int e = 0; e < 2; e++) {
                    float val = acc[mt][nt][h * 2 + e] + bcol[nt * 2 + e];
                    int col = n0 + nw * 64 + nt * 8 + 2 * t + e;
                    ins4(val, col, tv, ti);
                }
            }
            // merge across the 4 lanes of this row group
            #pragma unroll
            for (int msk = 1; msk <= 2; msk <<= 1) {
                float pv[4]; int pi[4];
                #pragma unroll
                for (int j = 0; j < 4; j++) {
                    pv[j] = __shfl_xor_sync(0xffffffffu, tv[j], msk);
                    pi[j] = __shfl_xor_sync(0xffffffffu, ti[j], msk);
                }
                #pragma unroll
                for (int j = 0; j < 4; j++) ins4(pv[j], pi[j], tv, ti);
            }
            if (t == 0) {
                int lrow = mw * 32 + mt * 16 + h * 8 + g;
                #pragma unroll
                for (int j = 0; j < 4; j++) {
                    svv[(lrow * 2 + nw) * 4 + j] = tv[j];
                    sii[(lrow * 2 + nw) * 4 + j] = ti[j];
                }
            }
        }
    }
    __syncthreads();
    if (tid < 128) {
        float tv[4]; int ti[4];
        #pragma unroll
        for (int j = 0; j < 4; j++) { tv[j] = svv[(tid * 2) * 4 + j]; ti[j] = sii[(tid * 2) * 4 + j]; }
        #pragma unroll
        for (int j = 0; j < 4; j++) ins4(svv[(tid * 2 + 1) * 4 + j], sii[(tid * 2 + 1) * 4 + j], tv, ti);
        size_t base = ((size_t)(m0 + tid) * 4 + blockIdx.x) * 4;
        #pragma unroll
        for (int j = 0; j < 4; j++) { g_candV[base + j] = tv[j]; g_candI[base + j] = ti[j]; }
    }
}

// ---------------------------------------------------------------------------
// K3b: merge 16 candidates per row -> global top4, softmax, bucket push
// ---------------------------------------------------------------------------
__global__ __launch_bounds__(256) void k3b_merge()
{
    int warp = threadIdx.x >> 5, lane = threadIdx.x & 31;
    int row = blockIdx.x * 8 + warp;
    int b = row >> 13;
    float v = (lane < 16) ? g_candV[(size_t)row * 16 + lane] : -INFINITY;
    int  ix = (lane < 16) ? g_candI[(size_t)row * 16 + lane] : 0x7fffffff;

    float topv[4]; int topi[4];
    #pragma unroll
    for (int r = 0; r < 4; r++) {
        float mv = v; int mi = ix;
        #pragma unroll
        for (int off = 16; off > 0; off >>= 1) {
            float ov = __shfl_xor_sync(0xffffffffu, mv, off);
            int   oi = __shfl_xor_sync(0xffffffffu, mi, off);
            if (bet(ov, oi, mv, mi)) { mv = ov; mi = oi; }
        }
        topv[r] = mv; topi[r] = mi;
        if (lane < 16 && ix == mi) v = -INFINITY;
    }
    float mx = topv[0];
    float e0 = expf(topv[0] - mx), e1 = expf(topv[1] - mx);
    float e2 = expf(topv[2] - mx), e3 = expf(topv[3] - mx);
    float inv = 1.0f / (e0 + e1 + e2 + e3);
    if (lane < 4) {
        float ej = (lane == 0) ? e0 : (lane == 1) ? e1 : (lane == 2) ? e2 : e3;
        float wgt = SC_X * ej * inv;
        int bt = b * kNC + topi[lane];
        int pos = atomicAdd(&g_cnt[bt], 1);
        if (pos < CAP) {
            g_entR[(size_t)bt * CAP + pos] = row;
            g_entW[(size_t)bt * CAP + pos] = wgt;
        }
    }
}

// ---------------------------------------------------------------------------
// K3c: per-(b,target) gather-sum (4-way ILP, float4)
// ---------------------------------------------------------------------------
__global__ __launch_bounds__(256) void k3c_gather(
    const float* __restrict__ out, const float* __restrict__ ln_b_c)
{
    int bt = blockIdx.x;
    int t = bt & (kNC - 1);
    int sub = threadIdx.x >> 6, c = threadIdx.x & 63;
    int n = min(g_cnt[bt], CAP);
    const float4* ssf = (const float4*)(out + OFF_SSTATE);
    const float4* svf = (const float4*)(out + OFF_SVAL);
    float4 aS = {0,0,0,0}, aV = {0,0,0,0};
    for (int i = sub; i < n; i += 4) {
        int r   = g_entR[(size_t)bt * CAP + i];
        float w = g_entW[(size_t)bt * CAP + i];
        float4 s = ssf[(size_t)r * 64 + c];
        float4 vv = svf[(size_t)r * 64 + c];
        aS.x += w * s.x;  aS.y += w * s.y;  aS.z += w * s.z;  aS.w += w * s.w;
        aV.x += w * vv.x; aV.y += w * vv.y; aV.z += w * vv.z; aV.w += w * vv.w;
    }
    __shared__ float4 shS[4][64], shV[4][64];
    shS[sub][c] = aS; shV[sub][c] = aV;
    __syncthreads();
    if (sub == 0) {
        float4 S = shS[0][c], V = shV[0][c];
        #pragma unroll
        for (int q = 1; q < 4; q++) {
            float4 s2 = shS[q][c], v2 = shV[q][c];
            S.x += s2.x; S.y += s2.y; S.z += s2.z; S.w += s2.w;
            V.x += v2.x; V.y += v2.y; V.z += v2.z; V.w += v2.w;
        }
        ((float4*)g_ncs)[(size_t)bt * 64 + c] = S;
        float4 nb = ((const float4*)ln_b_c)[c];
        V.x += nb.x; V.y += nb.y; V.z += nb.z; V.w += nb.w;
        #pragma unroll
        for (int j = 0; j < 4; j++)
            if (g_ic[j] == t) {
                float w = SC_B * g_wc[j];
                float4 es = ((const float4*)g_esum)[c];
                V.x += w * es.x; V.y += w * es.y; V.z += w * es.z; V.w += w * es.w;
            }
        ((float4*)g_ncv)[(size_t)bt * 64 + c] = V;
    }
}

// ---------------------------------------------------------------------------
// K4a: per-batch scores sc = (ncs*w_pair_c) @ ncs^T * INV_SQRT_D
// ---------------------------------------------------------------------------
__global__ __launch_bounds__(256) void k4a_scores(const float* __restrict__ wpc)
{
    int bb = blockIdx.z;
    int m0 = blockIdx.y * 64;
    int n0 = blockIdx.x * 64;
    const float* ncs = g_ncs + (size_t)bb * kNC * kD;
    __shared__ float As[16][64 + 4];
    __shared__ float Bs[16][64 + 4];
    int tid = threadIdx.x;
    int ty = tid / 16, tx = tid % 16;
    float acc[4][4] = {};
    int lrow = tid / 4;
    int lk = (tid % 4) * 4;
    for (int k0 = 0; k0 < kD; k0 += 16) {
        float4 av = *(const float4*)&ncs[(size_t)(m0 + lrow) * kD + k0 + lk];
        float4 bv = *(const float4*)&ncs[(size_t)(n0 + lrow) * kD + k0 + lk];
        float4 wv = *(const float4*)&wpc[k0 + lk];
        As[lk + 0][lrow] = av.x * wv.x; As[lk + 1][lrow] = av.y * wv.y;
        As[lk + 2][lrow] = av.z * wv.z; As[lk + 3][lrow] = av.w * wv.w;
        Bs[lk + 0][lrow] = bv.x; Bs[lk + 1][lrow] = bv.y;
        Bs[lk + 2][lrow] = bv.z; Bs[lk + 3][lrow] = bv.w;
        __syncthreads();
        #pragma unroll
        for (int kk = 0; kk < 16; kk++) {
            float ar[4], br[4];
            #pragma unroll
            for (int i = 0; i < 4; i++) ar[i] = As[kk][ty * 4 + i];
            #pragma unroll
            for (int j = 0; j < 4; j++) br[j] = Bs[kk][tx * 4 + j];
            #pragma unroll
            for (int i = 0; i < 4; i++)
                #pragma unroll
                for (int j = 0; j < 4; j++)
                    acc[i][j] += ar[i] * br[j];
        }
        __syncthreads();
    }
    #pragma unroll
    for (int i = 0; i < 4; i++)
        #pragma unroll
        for (int j = 0; j < 4; j++)
            g_scmat[(size_t)bb * kNC * kNC + (size_t)(m0 + ty * 4 + i) * kNC + (n0 + tx * 4 + j)] =
                acc[i][j] * INV_SQRT_D;
}

// ---------------------------------------------------------------------------
// K4b: per-(b,n) top-4 over 512 scores, softmax, gather, tanh/LN finalize
// ---------------------------------------------------------------------------
__global__ __launch_bounds__(256) void k4b_final(
    const float* __restrict__ ln_g_c, const float* __restrict__ ln_b_c,
    float* __restrict__ out)
{
    int bn = blockIdx.x;
    int bb = bn / kNC;
    int d = threadIdx.x;
    const float* sc = g_scmat + (size_t)bn * kNC;
    __shared__ float sv[256]; __shared__ int si[256];
    __shared__ float red[256];
    __shared__ float topw[4]; __shared__ int topidx[4];

    float v0 = sc[d], v1 = sc[d + 256];
    bool t0 = false, t1 = false;
    for (int r = 0; r < 4; r++) {
        float bv = -INFINITY; int bi = 0x7fffffff;
        if (!t0) { bv = v0; bi = d; }
        if (!t1 && bet(v1, d + 256, bv, bi)) { bv = v1; bi = d + 256; }
        sv[d] = bv; si[d] = bi; __syncthreads();
        for (int s = 128; s > 0; s >>= 1) {
            if (d < s && bet(sv[d + s], si[d + s], sv[d], si[d])) {
                sv[d] = sv[d + s]; si[d] = si[d + s];
            }
            __syncthreads();
        }
        if (d == 0) { topw[r] = sv[0]; topidx[r] = si[0]; }
        __syncthreads();
        int widx = topidx[r];
        if (widx == d) t0 = true;
        if (widx == d + 256) t1 = true;
    }

    float mx = topw[0];
    float e[4]; float esum = 0.0f;
    #pragma unroll
    for (int j = 0; j < 4; j++) { e[j] = expf(topw[j] - mx); esum += e[j]; }
    float inv = 1.0f / esum;

    const float* ncsB = g_ncs + (size_t)bb * kNC * kD;
    const float* ncvB = g_ncv + (size_t)bb * kNC * kD;
    float ds = 0.0f, dv = 0.0f;
    #pragma unroll
    for (int j = 0; j < 4; j++) {
        int m = topidx[j];
        float a = e[j] * inv;
        ds += a * ncsB[(size_t)m * kD + d];
        dv += a * ncvB[(size_t)m * kD + d];
    }
    float spre = g_ncs[(size_t)bn * kD + d];
    float vpre = g_ncv[(size_t)bn * kD + d];

    out[OFF_NCS + (size_t)bn * kD + d] = tanhf(spre + SC_B * ds);

    auto bsum = [&](float x) -> float {
        red[d] = x; __syncthreads();
        for (int s = 128; s > 0; s >>= 1) {
            if (d < s) red[d] += red[d + s];
            __syncthreads();
        }
        float r = red[0]; __syncthreads(); return r;
    };
    float x = vpre + SC_B * dv;
    float m = bsum(x) * (1.0f / kD);
    float xd = x - m;
    float var = bsum(xd * xd) * (1.0f / kD);
    out[OFF_NCV + (size_t)bn * kD + d] = xd * rsqrtf(var + EPSL) * ln_g_c[d] + ln_b_c[d];
}

// ---------------------------------------------------------------------------
extern "C" void kernel_launch(void* const* d_in, const int* in_sizes, int n_in,
                              void* d_out, int out_size) {
    const float* s_state  = (const float*)d_in[0];
    const float* s_val    = (const float*)d_in[1];
    const float* w_pair_s = (const float*)d_in[2];
    const float* w_pair_c = (const float*)d_in[4];
    const float* b_expand = (const float*)d_in[6];
    const float* b_b2s    = (const float*)d_in[8];
    const float* b_comp   = (const float*)d_in[10];
    const float* W_s2b    = (const float*)d_in[11];
    const float* b_s2b    = (const float*)d_in[12];
    const float* ln_g_s   = (const float*)d_in[13];
    const float* ln_b_s   = (const float*)d_in[14];
    const float* ln_g_e   = (const float*)d_in[15];
    const float* ln_b_e   = (const float*)d_in[16];
    const float* ln_g_c   = (const float*)d_in[17];
    const float* ln_b_c   = (const float*)d_in[18];
    float* out = (float*)d_out;

    k0_prep<<<1, 256>>>(b_expand, b_b2s, b_comp, ln_b_c, ln_g_e, ln_b_e);
    k1_splitW<<<dim3(kNC / 32, kD / 32), dim3(32, 32)>>>(W_s2b);
    k2_window<<<kM / 8, 256>>>(s_state, s_val, w_pair_s, ln_g_s, ln_b_s, out);
    k3a_gemm<<<dim3(kNC / 128, kM / 128), 256>>>(b_s2b);
    k3b_merge<<<kM / 8, 256>>>();
    k3c_gather<<<kB * kNC, 256>>>(out, ln_b_c);
    k4a_scores<<<dim3(kNC / 64, kNC / 64, kB), 256>>>(w_pair_c);
    k4b_final<<<kB * kNC, 256>>>(ln_g_c, ln_b_c, out);
}

// round 4
// speedup vs baseline: 1.7119x; 1.0498x over previous
#include <cuda_runtime.h>
#include <cuda_bf16.h>
#include <math.h>

// ---------------------------------------------------------------------------
#define kD   256
#define kB   4
#define kS   8192
#define kNE  2048
#define kNC  512
#define kWIN 4
#define kM   (kB * kS)

#define S_SC       0.25f
#define SC_B       0.2f
#define SC_X       0.075f
#define EPSL       1e-5f
#define INV_SQRT_D 0.0625f
#define CAP        2048

#define OFF_SSTATE ((size_t)0)
#define OFF_SVAL   ((size_t)kB * kS * kD)
#define OFF_NCS    ((size_t)2 * kB * kS * kD)
#define OFF_NCV    (OFF_NCS + (size_t)kB * kNC * kD)

// ---------------------------------------------------------------------------
__device__ float g_scmat[(size_t)kB * kNC * kNC];
__device__ int   g_entR[(size_t)kB * kNC * CAP];
__device__ float g_entW[(size_t)kB * kNC * CAP];
__device__ int   g_cnt[kB * kNC];
__device__ float g_esum[kD];
__device__ int   g_is[4]; __device__ float g_ws[4];
__device__ int   g_ic[4]; __device__ float g_wc[4];
__device__ float g_ncs[(size_t)kB * kNC * kD];
__device__ float g_ncv[(size_t)kB * kNC * kD];

__device__ __nv_bfloat16 g_shi[(size_t)kM * kD];
__device__ __nv_bfloat16 g_slo[(size_t)kM * kD];
__device__ __nv_bfloat16 g_wth[(size_t)kNC * kD];
__device__ __nv_bfloat16 g_wtl[(size_t)kNC * kD];
__device__ float g_candV[(size_t)kM * 16];
__device__ int   g_candI[(size_t)kM * 16];

__device__ __forceinline__ bool bet(float v, int i, float bv, int bi) {
    return (v > bv) || (v == bv && i < bi);
}

__device__ __forceinline__ float warpsum(float v) {
    #pragma unroll
    for (int off = 16; off > 0; off >>= 1) v += __shfl_xor_sync(0xffffffffu, v, off);
    return v;
}

__device__ __forceinline__ void ins4(float v, int i, float* tv, int* ti) {
    if (bet(v, i, tv[3], ti[3])) {
        tv[3] = v; ti[3] = i;
        #pragma unroll
        for (int q = 3; q > 0; q--) {
            if (bet(tv[q], ti[q], tv[q - 1], ti[q - 1])) {
                float fv = tv[q]; tv[q] = tv[q - 1]; tv[q - 1] = fv;
                int   fi = ti[q]; ti[q] = ti[q - 1]; ti[q - 1] = fi;
            } else break;
        }
    }
}

__device__ __forceinline__ void mma16816(float* c, const unsigned* a, const unsigned* b) {
    asm volatile(
        "mma.sync.aligned.m16n8k16.row.col.f32.bf16.bf16.f32 "
        "{%0,%1,%2,%3}, {%4,%5,%6,%7}, {%8,%9}, {%0,%1,%2,%3};"
        : "+f"(c[0]), "+f"(c[1]), "+f"(c[2]), "+f"(c[3])
        : "r"(a[0]), "r"(a[1]), "r"(a[2]), "r"(a[3]), "r"(b[0]), "r"(b[1]));
}

__device__ __forceinline__ void ldsm4(unsigned* r, const void* p) {
    unsigned a = (unsigned)__cvta_generic_to_shared(p);
    asm volatile("ldmatrix.sync.aligned.m8n8.x4.shared.b16 {%0,%1,%2,%3}, [%4];"
        : "=r"(r[0]), "=r"(r[1]), "=r"(r[2]), "=r"(r[3]) : "r"(a));
}

__device__ __forceinline__ void cpasync16(void* dst, const void* src) {
    unsigned sd = (unsigned)__cvta_generic_to_shared(dst);
    asm volatile("cp.async.cg.shared.global [%0], [%1], 16;" :: "r"(sd), "l"(src));
}

// ---------------------------------------------------------------------------
// K0: prep (top4 of biases, collapsed e_val algebra, zero counters)
// ---------------------------------------------------------------------------
__global__ __launch_bounds__(256) void k0_prep(
    const float* __restrict__ b_expand, const float* __restrict__ b_b2s,
    const float* __restrict__ b_comp,   const float* __restrict__ ln_b_c,
    const float* __restrict__ ln_g_e,   const float* __restrict__ ln_b_e)
{
    __shared__ float sv[256];  __shared__ int si[256];
    __shared__ float red[256];
    __shared__ float tv[4];    __shared__ int ti[4];
    __shared__ float we[4];    __shared__ int ie[4];
    int tid = threadIdx.x;

    for (int j = tid; j < kB * kNC; j += 256) g_cnt[j] = 0;

    auto top4 = [&](const float* x, int n) {
        for (int r = 0; r < 4; r++) {
            float bv = -INFINITY; int bi = 0x7fffffff;
            for (int j = tid; j < n; j += 256) {
                bool skip = false;
                for (int q = 0; q < r; q++) if (ti[q] == j) skip = true;
                float v = x[j];
                if (!skip && bet(v, j, bv, bi)) { bv = v; bi = j; }
            }
            sv[tid] = bv; si[tid] = bi; __syncthreads();
            for (int s = 128; s > 0; s >>= 1) {
                if (tid < s && bet(sv[tid + s], si[tid + s], sv[tid], si[tid])) {
                    sv[tid] = sv[tid + s]; si[tid] = si[tid + s];
                }
                __syncthreads();
            }
            if (tid == 0) { tv[r] = sv[0]; ti[r] = si[0]; }
            __syncthreads();
        }
    };
    auto softmax4 = [&](float* wout) {
        if (tid == 0) {
            float m = tv[0];
            float e0 = expf(tv[0] - m), e1 = expf(tv[1] - m);
            float e2 = expf(tv[2] - m), e3 = expf(tv[3] - m);
            float inv = 1.0f / (e0 + e1 + e2 + e3);
            wout[0] = e0 * inv; wout[1] = e1 * inv;
            wout[2] = e2 * inv; wout[3] = e3 * inv;
        }
        __syncthreads();
    };

    top4(b_expand, kNE); softmax4(we);
    if (tid < 4) ie[tid] = ti[tid];
    __syncthreads();
    top4(b_b2s, kS); softmax4(g_ws);
    if (tid < 4) g_is[tid] = ti[tid];
    __syncthreads();
    top4(b_comp, kNC); softmax4(g_wc);
    if (tid < 4) g_ic[tid] = ti[tid];
    __syncthreads();

    int d = tid;
    float cval = ln_b_c[d];
    float rowval[4];
    float dvE = 0.0f;
    #pragma unroll
    for (int j = 0; j < 4; j++) {
        rowval[j] = SC_B * (float)kNC * we[j] * cval;
        if (ie[j] < 4) dvE += rowval[j];
    }
    dvE *= 0.25f;
    float base = SC_B * dvE;

    auto bsum = [&](float x) -> float {
        red[tid] = x; __syncthreads();
        for (int s = 128; s > 0; s >>= 1) {
            if (tid < s) red[tid] += red[tid + s];
            __syncthreads();
        }
        float r = red[0]; __syncthreads(); return r;
    };
    float ge = ln_g_e[d], be = ln_b_e[d];
    auto LN_e = [&](float x) -> float {
        float m  = bsum(x) * (1.0f / kD);
        float dv = x - m;
        float var = bsum(dv * dv) * (1.0f / kD);
        return dv * rsqrtf(var + EPSL) * ge + be;
    };

    float other = LN_e(base);
    float esum = (float)(kNE - 4) * other;
    #pragma unroll
    for (int j = 0; j < 4; j++) esum += LN_e(rowval[j] + base);
    g_esum[d] = esum;
}

// ---------------------------------------------------------------------------
// K1: split W_s2b into transposed bf16 hi/lo  [512 n][256 k]
// ---------------------------------------------------------------------------
__global__ void k1_splitW(const float* __restrict__ W)
{
    __shared__ float tile[32][33];
    int n0 = blockIdx.x * 32, k0 = blockIdx.y * 32;
    int tx = threadIdx.x, ty = threadIdx.y;
    tile[ty][tx] = W[(size_t)(k0 + ty) * kNC + n0 + tx];
    __syncthreads();
    float x = tile[tx][ty];
    __nv_bfloat16 hi = __float2bfloat16(x);
    float lo = x - __bfloat162float(hi);
    g_wth[(size_t)(n0 + ty) * kD + k0 + tx] = hi;
    g_wtl[(size_t)(n0 + ty) * kD + k0 + tx] = __float2bfloat16(lo);
}

// ---------------------------------------------------------------------------
// K2: warp-per-row window prop + double tanh + double LN; emits bf16 split
// ---------------------------------------------------------------------------
__global__ __launch_bounds__(256) void k2_window(
    const float* __restrict__ s_state, const float* __restrict__ s_val,
    const float* __restrict__ w_pair_s,
    const float* __restrict__ ln_g_s, const float* __restrict__ ln_b_s,
    float* __restrict__ out)
{
    int warp = threadIdx.x >> 5, lane = threadIdx.x & 31;
    int row = blockIdx.x * 8 + warp;
    int b = row >> 13, n = row & (kS - 1);
    const float4* st4 = (const float4*)(s_state + (size_t)b * kS * kD);
    const float4* vl4 = (const float4*)(s_val   + (size_t)b * kS * kD);
    int ci = lane * 2;

    float4 w0 = ((const float4*)w_pair_s)[ci];
    float4 w1 = ((const float4*)w_pair_s)[ci + 1];
    float4 s0a = st4[(size_t)n * 64 + ci];
    float4 s0b = st4[(size_t)n * 64 + ci + 1];
    float4 q0, q1;
    q0.x = s0a.x * w0.x; q0.y = s0a.y * w0.y; q0.z = s0a.z * w0.z; q0.w = s0a.w * w0.w;
    q1.x = s0b.x * w1.x; q1.y = s0b.y * w1.y; q1.z = s0b.z * w1.z; q1.w = s0b.w * w1.w;

    float sc[9];
    #pragma unroll
    for (int k = 0; k < 9; k++) {
        int j = n + k - kWIN;
        bool valid = ((unsigned)j < (unsigned)kS);
        int jc = min(max(j, 0), kS - 1);
        float4 na = st4[(size_t)jc * 64 + ci];
        float4 nb = st4[(size_t)jc * 64 + ci + 1];
        float p = q0.x * na.x + q0.y * na.y + q0.z * na.z + q0.w * na.w
                + q1.x * nb.x + q1.y * nb.y + q1.z * nb.z + q1.w * nb.w;
        p = warpsum(p);
        sc[k] = valid ? p * INV_SQRT_D : -1e30f;
    }
    float mx = sc[0];
    #pragma unroll
    for (int k = 1; k < 9; k++) mx = fmaxf(mx, sc[k]);
    float asum = 0.0f;
    #pragma unroll
    for (int k = 0; k < 9; k++) { sc[k] = expf(sc[k] - mx); asum += sc[k]; }
    float ainv = 1.0f / asum;

    float4 ds0 = {0,0,0,0}, ds1 = {0,0,0,0}, dv0 = {0,0,0,0}, dv1 = {0,0,0,0};
    #pragma unroll
    for (int k = 0; k < 9; k++) {
        int j = n + k - kWIN;
        int jc = min(max(j, 0), kS - 1);
        float a = sc[k] * ainv;
        float4 na = st4[(size_t)jc * 64 + ci];
        float4 nb = st4[(size_t)jc * 64 + ci + 1];
        float4 va = vl4[(size_t)jc * 64 + ci];
        float4 vb = vl4[(size_t)jc * 64 + ci + 1];
        ds0.x += a * na.x; ds0.y += a * na.y; ds0.z += a * na.z; ds0.w += a * na.w;
        ds1.x += a * nb.x; ds1.y += a * nb.y; ds1.z += a * nb.z; ds1.w += a * nb.w;
        dv0.x += a * va.x; dv0.y += a * va.y; dv0.z += a * va.z; dv0.w += a * va.w;
        dv1.x += a * vb.x; dv1.y += a * vb.y; dv1.z += a * vb.z; dv1.w += a * vb.w;
    }

    float so[8];
    so[0] = tanhf(tanhf(s0a.x + S_SC * ds0.x));
    so[1] = tanhf(tanhf(s0a.y + S_SC * ds0.y));
    so[2] = tanhf(tanhf(s0a.z + S_SC * ds0.z));
    so[3] = tanhf(tanhf(s0a.w + S_SC * ds0.w));
    so[4] = tanhf(tanhf(s0b.x + S_SC * ds1.x));
    so[5] = tanhf(tanhf(s0b.y + S_SC * ds1.y));
    so[6] = tanhf(tanhf(s0b.z + S_SC * ds1.z));
    so[7] = tanhf(tanhf(s0b.w + S_SC * ds1.w));

    float4* outS = (float4*)(out + OFF_SSTATE);
    outS[(size_t)row * 64 + ci]     = make_float4(so[0], so[1], so[2], so[3]);
    outS[(size_t)row * 64 + ci + 1] = make_float4(so[4], so[5], so[6], so[7]);

    uint4 hw, lw;
    unsigned* hwp = (unsigned*)&hw; unsigned* lwp = (unsigned*)&lw;
    #pragma unroll
    for (int i = 0; i < 4; i++) {
        float a = so[2 * i], c = so[2 * i + 1];
        __nv_bfloat16 ha = __float2bfloat16(a), hc = __float2bfloat16(c);
        hwp[i] = ((unsigned)__bfloat16_as_ushort(hc) << 16) | __bfloat16_as_ushort(ha);
        float la = a - __bfloat162float(ha), lc = c - __bfloat162float(hc);
        __nv_bfloat16 bla = __float2bfloat16(la), blc = __float2bfloat16(lc);
        lwp[i] = ((unsigned)__bfloat16_as_ushort(blc) << 16) | __bfloat16_as_ushort(bla);
    }
    *(uint4*)&g_shi[(size_t)row * kD + lane * 8] = hw;
    *(uint4*)&g_slo[(size_t)row * kD + lane * 8] = lw;

    float4 va0 = vl4[(size_t)n * 64 + ci];
    float4 va1 = vl4[(size_t)n * 64 + ci + 1];
    float v[8];
    v[0] = va0.x + S_SC * dv0.x; v[1] = va0.y + S_SC * dv0.y;
    v[2] = va0.z + S_SC * dv0.z; v[3] = va0.w + S_SC * dv0.w;
    v[4] = va1.x + S_SC * dv1.x; v[5] = va1.y + S_SC * dv1.y;
    v[6] = va1.z + S_SC * dv1.z; v[7] = va1.w + S_SC * dv1.w;

    float4 g0 = ((const float4*)ln_g_s)[ci], g1 = ((const float4*)ln_g_s)[ci + 1];
    float4 b0v = ((const float4*)ln_b_s)[ci], b1v = ((const float4*)ln_b_s)[ci + 1];
    float gs[8] = {g0.x, g0.y, g0.z, g0.w, g1.x, g1.y, g1.z, g1.w};
    float bs[8] = {b0v.x, b0v.y, b0v.z, b0v.w, b1v.x, b1v.y, b1v.z, b1v.w};

    float s8 = 0.0f;
    #pragma unroll
    for (int i = 0; i < 8; i++) s8 += v[i];
    float mean = warpsum(s8) * (1.0f / kD);
    float vs = 0.0f;
    #pragma unroll
    for (int i = 0; i < 8; i++) { v[i] -= mean; vs += v[i] * v[i]; }
    float rstd = rsqrtf(warpsum(vs) * (1.0f / kD) + EPSL);
    #pragma unroll
    for (int i = 0; i < 8; i++) v[i] = v[i] * rstd * gs[i] + bs[i];

    bool hit = false; float wj = 0.0f;
    #pragma unroll
    for (int j = 0; j < 4; j++)
        if (g_is[j] == n) { hit = true; wj = g_ws[j]; }
    if (hit) {
        float4 e0 = ((const float4*)g_esum)[ci], e1 = ((const float4*)g_esum)[ci + 1];
        float es[8] = {e0.x, e0.y, e0.z, e0.w, e1.x, e1.y, e1.z, e1.w};
        #pragma unroll
        for (int i = 0; i < 8; i++) v[i] += SC_X * wj * es[i];
    }

    s8 = 0.0f;
    #pragma unroll
    for (int i = 0; i < 8; i++) s8 += v[i];
    mean = warpsum(s8) * (1.0f / kD);
    vs = 0.0f;
    #pragma unroll
    for (int i = 0; i < 8; i++) { v[i] -= mean; vs += v[i] * v[i]; }
    rstd = rsqrtf(warpsum(vs) * (1.0f / kD) + EPSL);
    float4* outV = (float4*)(out + OFF_SVAL);
    outV[(size_t)row * 64 + ci] =
        make_float4(v[0] * rstd * gs[0] + bs[0], v[1] * rstd * gs[1] + bs[1],
                    v[2] * rstd * gs[2] + bs[2], v[3] * rstd * gs[3] + bs[3]);
    outV[(size_t)row * 64 + ci + 1] =
        make_float4(v[4] * rstd * gs[4] + bs[4], v[5] * rstd * gs[5] + bs[5],
                    v[6] * rstd * gs[6] + bs[6], v[7] * rstd * gs[7] + bs[7]);
}

// ---------------------------------------------------------------------------
// K3a: split-bf16 tensor-core GEMM, cp.async double-buffered + ldmatrix,
// fused per-slab top4 epilogue. 128x128 tile, K-chunk 16, 2 stages.
// Smem row stride 24 bf16 (48B): conflict-free for LDSM & 16B-aligned cp.async
// ---------------------------------------------------------------------------
#define KC 16
#define SROW 24
__global__ __launch_bounds__(256, 2) void k3a_gemm(const float* __restrict__ bias)
{
    // [stage][array: Ah,Al,Bh,Bl][128 * SROW]  = 2*4*128*24*2B = 49152B
    __shared__ __align__(16) __nv_bfloat16 sm[2][4][128 * SROW];
    int tid = threadIdx.x;
    int warp = tid >> 5, lane = tid & 31;
    int mw = warp & 3, nw = warp >> 2;
    int g = lane >> 2, t = lane & 3;
    int m0 = blockIdx.y * 128, n0 = blockIdx.x * 128;

    // cp.async mapping: 256 threads x one 16B chunk per array per stage
    int lrow = tid >> 1, lhalf = tid & 1;
    const __nv_bfloat16* srcAh = g_shi + (size_t)(m0 + lrow) * kD + lhalf * 8;
    const __nv_bfloat16* srcAl = g_slo + (size_t)(m0 + lrow) * kD + lhalf * 8;
    const __nv_bfloat16* srcBh = g_wth + (size_t)(n0 + lrow) * kD + lhalf * 8;
    const __nv_bfloat16* srcBl = g_wtl + (size_t)(n0 + lrow) * kD + lhalf * 8;
    int dOff = lrow * SROW + lhalf * 8;

    // ldmatrix lane addressing
    int a_row = mw * 32 + (lane & 7) + ((lane >> 3) & 1) * 8;   // + mt*16
    int a_kh  = ((lane >> 4) & 1) * 8;
    int b_row = nw * 64 + (lane & 7) + ((lane >> 4) & 1) * 8;   // + p*16
    int b_kh  = ((lane >> 3) & 1) * 8;

    float acc[2][8][4];
    #pragma unroll
    for (int i = 0; i < 2; i++)
        #pragma unroll
        for (int j = 0; j < 8; j++)
            #pragma unroll
            for (int q = 0; q < 4; q++) acc[i][j][q] = 0.0f;

    auto load_stage = [&](int st, int k0) {
        cpasync16(&sm[st][0][dOff], srcAh + k0);
        cpasync16(&sm[st][1][dOff], srcAl + k0);
        cpasync16(&sm[st][2][dOff], srcBh + k0);
        cpasync16(&sm[st][3][dOff], srcBl + k0);
        asm volatile("cp.async.commit_group;");
    };

    load_stage(0, 0);

    #pragma unroll 4
    for (int ks = 0; ks < kD / KC; ks++) {
        int st = ks & 1;
        if (ks + 1 < kD / KC) {
            load_stage(st ^ 1, (ks + 1) * KC);
            asm volatile("cp.async.wait_group 1;");
        } else {
            asm volatile("cp.async.wait_group 0;");
        }
        __syncthreads();

        unsigned ah[2][4], al[2][4];
        #pragma unroll
        for (int mt = 0; mt < 2; mt++) {
            ldsm4(ah[mt], &sm[st][0][(a_row + mt * 16) * SROW + a_kh]);
            ldsm4(al[mt], &sm[st][1][(a_row + mt * 16) * SROW + a_kh]);
        }
        #pragma unroll
        for (int p = 0; p < 4; p++) {
            unsigned bh[4], bl[4];
            ldsm4(bh, &sm[st][2][(b_row + p * 16) * SROW + b_kh]);
            ldsm4(bl, &sm[st][3][(b_row + p * 16) * SROW + b_kh]);
            #pragma unroll
            for (int half = 0; half < 2; half++) {
                int nt = p * 2 + half;
                unsigned* bhp = bh + half * 2;
                unsigned* blp = bl + half * 2;
                #pragma unroll
                for (int mt = 0; mt < 2; mt++) {
                    mma16816(acc[mt][nt], ah[mt], bhp);
                    mma16816(acc[mt][nt], ah[mt], blp);
                    mma16816(acc[mt][nt], al[mt], bhp);
                }
            }
        }
        __syncthreads();
    }

    float bcol[16];
    #pragma unroll
    for (int nt = 0; nt < 8; nt++) {
        int c = n0 + nw * 64 + nt * 8 + 2 * t;
        bcol[nt * 2]     = bias[c];
        bcol[nt * 2 + 1] = bias[c + 1];
    }

    float* svv = (float*)&sm[0][0][0];
    int*   sii = (int*)(((char*)&sm[0][0][0]) + 4096);

    #pragma unroll
    for (int mt = 0; mt < 2; mt++) {
        #pragma unroll
        for (int h = 0; h < 2; h++) {
            float tv[4] = {-INFINITY, -INFINITY, -INFINITY, -INFINITY};
            int   ti[4] = {0x7fffffff, 0x7fffffff, 0x7fffffff, 0x7fffffff};
            #pragma unroll
            for (int nt = 0; nt < 8; nt++) {
                #pragma unroll
                for (int e = 0; e < 2; e++) {
                    float val = acc[mt][nt][h * 2 + e] + bcol[nt * 2 + e];
                    int col = n0 + nw * 64 + nt * 8 + 2 * t + e;
                    ins4(val, col, tv, ti);
                }
            }
            #pragma unroll
            for (int msk = 1; msk <= 2; msk <<= 1) {
                float pv[4]; int pi[4];
                #pragma unroll
                for (int j = 0; j < 4; j++) {
                    pv[j] = __shfl_xor_sync(0xffffffffu, tv[j], msk);
                    pi[j] = __shfl_xor_sync(0xffffffffu, ti[j], msk);
                }
                #pragma unroll
                for (int j = 0; j < 4; j++) ins4(pv[j], pi[j], tv, ti);
            }
            if (t == 0) {
                int lrow2 = mw * 32 + mt * 16 + h * 8 + g;
                #pragma unroll
                for (int j = 0; j < 4; j++) {
                    svv[(lrow2 * 2 + nw) * 4 + j] = tv[j];
                    sii[(lrow2 * 2 + nw) * 4 + j] = ti[j];
                }
            }
        }
    }
    __syncthreads();
    if (tid < 128) {
        float tv[4]; int ti[4];
        #pragma unroll
        for (int j = 0; j < 4; j++) { tv[j] = svv[(tid * 2) * 4 + j]; ti[j] = sii[(tid * 2) * 4 + j]; }
        #pragma unroll
        for (int j = 0; j < 4; j++) ins4(svv[(tid * 2 + 1) * 4 + j], sii[(tid * 2 + 1) * 4 + j], tv, ti);
        size_t base = ((size_t)(m0 + tid) * 4 + blockIdx.x) * 4;
        #pragma unroll
        for (int j = 0; j < 4; j++) { g_candV[base + j] = tv[j]; g_candI[base + j] = ti[j]; }
    }
}

// ---------------------------------------------------------------------------
// K3b: merge 16 candidates per row -> global top4, softmax, bucket push
// ---------------------------------------------------------------------------
__global__ __launch_bounds__(256) void k3b_merge()
{
    int warp = threadIdx.x >> 5, lane = threadIdx.x & 31;
    int row = blockIdx.x * 8 + warp;
    int b = row >> 13;
    float v = (lane < 16) ? g_candV[(size_t)row * 16 + lane] : -INFINITY;
    int  ix = (lane < 16) ? g_candI[(size_t)row * 16 + lane] : 0x7fffffff;

    float topv[4]; int topi[4];
    #pragma unroll
    for (int r = 0; r < 4; r++) {
        float mv = v; int mi = ix;
        #pragma unroll
        for (int off = 16; off > 0; off >>= 1) {
            float ov = __shfl_xor_sync(0xffffffffu, mv, off);
            int   oi = __shfl_xor_sync(0xffffffffu, mi, off);
            if (bet(ov, oi, mv, mi)) { mv = ov; mi = oi; }
        }
        topv[r] = mv; topi[r] = mi;
        if (lane < 16 && ix == mi) v = -INFINITY;
    }
    float mx = topv[0];
    float e0 = expf(topv[0] - mx), e1 = expf(topv[1] - mx);
    float e2 = expf(topv[2] - mx), e3 = expf(topv[3] - mx);
    float inv = 1.0f / (e0 + e1 + e2 + e3);
    if (lane < 4) {
        float ej = (lane == 0) ? e0 : (lane == 1) ? e1 : (lane == 2) ? e2 : e3;
        float wgt = SC_X * ej * inv;
        int bt = b * kNC + topi[lane];
        int pos = atomicAdd(&g_cnt[bt], 1);
        if (pos < CAP) {
            g_entR[(size_t)bt * CAP + pos] = row;
            g_entW[(size_t)bt * CAP + pos] = wgt;
        }
    }
}

// ---------------------------------------------------------------------------
// K3c: per-(b,target) gather-sum (4-way ILP, float4)
// ---------------------------------------------------------------------------
__global__ __launch_bounds__(256) void k3c_gather(
    const float* __restrict__ out, const float* __restrict__ ln_b_c)
{
    int bt = blockIdx.x;
    int t = bt & (kNC - 1);
    int sub = threadIdx.x >> 6, c = threadIdx.x & 63;
    int n = min(g_cnt[bt], CAP);
    const float4* ssf = (const float4*)(out + OFF_SSTATE);
    const float4* svf = (const float4*)(out + OFF_SVAL);
    float4 aS = {0,0,0,0}, aV = {0,0,0,0};
    for (int i = sub; i < n; i += 4) {
        int r   = g_entR[(size_t)bt * CAP + i];
        float w = g_entW[(size_t)bt * CAP + i];
        float4 s = ssf[(size_t)r * 64 + c];
        float4 vv = svf[(size_t)r * 64 + c];
        aS.x += w * s.x;  aS.y += w * s.y;  aS.z += w * s.z;  aS.w += w * s.w;
        aV.x += w * vv.x; aV.y += w * vv.y; aV.z += w * vv.z; aV.w += w * vv.w;
    }
    __shared__ float4 shS[4][64], shV[4][64];
    shS[sub][c] = aS; shV[sub][c] = aV;
    __syncthreads();
    if (sub == 0) {
        float4 S = shS[0][c], V = shV[0][c];
        #pragma unroll
        for (int q = 1; q < 4; q++) {
            float4 s2 = shS[q][c], v2 = shV[q][c];
            S.x += s2.x; S.y += s2.y; S.z += s2.z; S.w += s2.w;
            V.x += v2.x; V.y += v2.y; V.z += v2.z; V.w += v2.w;
        }
        ((float4*)g_ncs)[(size_t)bt * 64 + c] = S;
        float4 nb = ((const float4*)ln_b_c)[c];
        V.x += nb.x; V.y += nb.y; V.z += nb.z; V.w += nb.w;
        #pragma unroll
        for (int j = 0; j < 4; j++)
            if (g_ic[j] == t) {
                float w = SC_B * g_wc[j];
                float4 es = ((const float4*)g_esum)[c];
                V.x += w * es.x; V.y += w * es.y; V.z += w * es.z; V.w += w * es.w;
            }
        ((float4*)g_ncv)[(size_t)bt * 64 + c] = V;
    }
}

// ---------------------------------------------------------------------------
// K4a: per-batch scores sc = (ncs*w_pair_c) @ ncs^T * INV_SQRT_D
// ---------------------------------------------------------------------------
__global__ __launch_bounds__(256) void k4a_scores(const float* __restrict__ wpc)
{
    int bb = blockIdx.z;
    int m0 = blockIdx.y * 64;
    int n0 = blockIdx.x * 64;
    const float* ncs = g_ncs + (size_t)bb * kNC * kD;
    __shared__ float As[16][64 + 4];
    __shared__ float Bs[16][64 + 4];
    int tid = threadIdx.x;
    int ty = tid / 16, tx = tid % 16;
    float acc[4][4] = {};
    int lrow = tid / 4;
    int lk = (tid % 4) * 4;
    for (int k0 = 0; k0 < kD; k0 += 16) {
        float4 av = *(const float4*)&ncs[(size_t)(m0 + lrow) * kD + k0 + lk];
        float4 bv = *(const float4*)&ncs[(size_t)(n0 + lrow) * kD + k0 + lk];
        float4 wv = *(const float4*)&wpc[k0 + lk];
        As[lk + 0][lrow] = av.x * wv.x; As[lk + 1][lrow] = av.y * wv.y;
        As[lk + 2][lrow] = av.z * wv.z; As[lk + 3][lrow] = av.w * wv.w;
        Bs[lk + 0][lrow] = bv.x; Bs[lk + 1][lrow] = bv.y;
        Bs[lk + 2][lrow] = bv.z; Bs[lk + 3][lrow] = bv.w;
        __syncthreads();
        #pragma unroll
        for (int kk = 0; kk < 16; kk++) {
            float ar[4], br[4];
            #pragma unroll
            for (int i = 0; i < 4; i++) ar[i] = As[kk][ty * 4 + i];
            #pragma unroll
            for (int j = 0; j < 4; j++) br[j] = Bs[kk][tx * 4 + j];
            #pragma unroll
            for (int i = 0; i < 4; i++)
                #pragma unroll
                for (int j = 0; j < 4; j++)
                    acc[i][j] += ar[i] * br[j];
        }
        __syncthreads();
    }
    #pragma unroll
    for (int i = 0; i < 4; i++)
        #pragma unroll
        for (int j = 0; j < 4; j++)
            g_scmat[(size_t)bb * kNC * kNC + (size_t)(m0 + ty * 4 + i) * kNC + (n0 + tx * 4 + j)] =
                acc[i][j] * INV_SQRT_D;
}

// ---------------------------------------------------------------------------
// K4b: per-(b,n) top-4 over 512 scores, softmax, gather, tanh/LN finalize
// ---------------------------------------------------------------------------
__global__ __launch_bounds__(256) void k4b_final(
    const float* __restrict__ ln_g_c, const float* __restrict__ ln_b_c,
    float* __restrict__ out)
{
    int bn = blockIdx.x;
    int bb = bn / kNC;
    int d = threadIdx.x;
    const float* sc = g_scmat + (size_t)bn * kNC;
    __shared__ float sv[256]; __shared__ int si[256];
    __shared__ float red[256];
    __shared__ float topw[4]; __shared__ int topidx[4];

    float v0 = sc[d], v1 = sc[d + 256];
    bool t0 = false, t1 = false;
    for (int r = 0; r < 4; r++) {
        float bv = -INFINITY; int bi = 0x7fffffff;
        if (!t0) { bv = v0; bi = d; }
        if (!t1 && bet(v1, d + 256, bv, bi)) { bv = v1; bi = d + 256; }
        sv[d] = bv; si[d] = bi; __syncthreads();
        for (int s = 128; s > 0; s >>= 1) {
            if (d < s && bet(sv[d + s], si[d + s], sv[d], si[d])) {
                sv[d] = sv[d + s]; si[d] = si[d + s];
            }
            __syncthreads();
        }
        if (d == 0) { topw[r] = sv[0]; topidx[r] = si[0]; }
        __syncthreads();
        int widx = topidx[r];
        if (widx == d) t0 = true;
        if (widx == d + 256) t1 = true;
    }

    float mx = topw[0];
    float e[4]; float esum = 0.0f;
    #pragma unroll
    for (int j = 0; j < 4; j++) { e[j] = expf(topw[j] - mx); esum += e[j]; }
    float inv = 1.0f / esum;

    const float* ncsB = g_ncs + (size_t)bb * kNC * kD;
    const float* ncvB = g_ncv + (size_t)bb * kNC * kD;
    float ds = 0.0f, dv = 0.0f;
    #pragma unroll
    for (int j = 0; j < 4; j++) {
        int m = topidx[j];
        float a = e[j] * inv;
        ds += a * ncsB[(size_t)m * kD + d];
        dv += a * ncvB[(size_t)m * kD + d];
    }
    float spre = g_ncs[(size_t)bn * kD + d];
    float vpre = g_ncv[(size_t)bn * kD + d];

    out[OFF_NCS + (size_t)bn * kD + d] = tanhf(spre + SC_B * ds);

    auto bsum = [&](float x) -> float {
        red[d] = x; __syncthreads();
        for (int s = 128; s > 0; s >>= 1) {
            if (d < s) red[d] += red[d + s];
            __syncthreads();
        }
        float r = red[0]; __syncthreads(); return r;
    };
    float x = vpre + SC_B * dv;
    float m = bsum(x) * (1.0f / kD);
    float xd = x - m;
    float var = bsum(xd * xd) * (1.0f / kD);
    out[OFF_NCV + (size_t)bn * kD + d] = xd * rsqrtf(var + EPSL) * ln_g_c[d] + ln_b_c[d];
}

// ---------------------------------------------------------------------------
extern "C" void kernel_launch(void* const* d_in, const int* in_sizes, int n_in,
                              void* d_out, int out_size) {
    const float* s_state  = (const float*)d_in[0];
    const float* s_val    = (const float*)d_in[1];
    const float* w_pair_s = (const float*)d_in[2];
    const float* w_pair_c = (const float*)d_in[4];
    const float* b_expand = (const float*)d_in[6];
    const float* b_b2s    = (const float*)d_in[8];
    const float* b_comp   = (const float*)d_in[10];
    const float* W_s2b    = (const float*)d_in[11];
    const float* b_s2b    = (const float*)d_in[12];
    const float* ln_g_s   = (const float*)d_in[13];
    const float* ln_b_s   = (const float*)d_in[14];
    const float* ln_g_e   = (const float*)d_in[15];
    const float* ln_b_e   = (const float*)d_in[16];
    const float* ln_g_c   = (const float*)d_in[17];
    const float* ln_b_c   = (const float*)d_in[18];
    float* out = (float*)d_out;

    k0_prep<<<1, 256>>>(b_expand, b_b2s, b_comp, ln_b_c, ln_g_e, ln_b_e);
    k1_splitW<<<dim3(kNC / 32, kD / 32), dim3(32, 32)>>>(W_s2b);
    k2_window<<<kM / 8, 256>>>(s_state, s_val, w_pair_s, ln_g_s, ln_b_s, out);
    k3a_gemm<<<dim3(kNC / 128, kM / 128), 256>>>(b_s2b);
    k3b_merge<<<kM / 8, 256>>>();
    k3c_gather<<<kB * kNC, 256>>>(out, ln_b_c);
    k4a_scores<<<dim3(kNC / 64, kNC / 64, kB), 256>>>(w_pair_c);
    k4b_final<<<kB * kNC, 256>>>(ln_g_c, ln_b_c, out);
}